// round 1
// baseline (speedup 1.0000x reference)
#include <cuda_runtime.h>
#include <cstdint>
#include <cstddef>

#define H        256
#define AF       39
#define BF       11
#define KI       50
#define KO_REAL  295
#define KO_PAD   304
#define EMAX     380000
#define NMAX     200000
#define BM       64
#define BK       16

// ---------------- scratch (device globals; no runtime allocation) ----------
__device__ float g_msg_input[(size_t)EMAX * H];
__device__ float g_msgA[(size_t)EMAX * H];
__device__ float g_msgB[(size_t)EMAX * H];
__device__ float g_S[(size_t)NMAX * H];
__device__ float g_WiT[KI * H];
__device__ float g_WhT[H * H];
__device__ float g_WoT[KO_PAD * H];

// ---------------- helpers ---------------------------------------------------
__device__ __forceinline__ void red_add4(float* p, float a, float b, float c, float d) {
  asm volatile("red.global.add.v4.f32 [%0], {%1,%2,%3,%4};"
               :: "l"(p), "f"(a), "f"(b), "f"(c), "f"(d) : "memory");
}

// transpose W[h][Kreal] (row-major) -> WT[k][h], zero-padded to Kout rows
__global__ void k_transpose(float* __restrict__ dst, const float* __restrict__ src,
                            int Kout, int Kreal) {
  int idx = blockIdx.x * blockDim.x + threadIdx.x;
  if (idx >= Kout * H) return;
  int k = idx >> 8, h = idx & (H - 1);
  dst[idx] = (k < Kreal) ? src[h * Kreal + k] : 0.f;
}

// ---------------- init: msg_input = concat(x[src], bond) @ W_i^T ------------
// dynamic smem: As[KI][BM] + Bs[KI][H]
__global__ __launch_bounds__(256) void k_init(
    const float* __restrict__ x, const float* __restrict__ bond,
    const int* __restrict__ esrc, const float* __restrict__ WiT,
    float* __restrict__ msg_input, float* __restrict__ msg0, int E)
{
  extern __shared__ float sm[];
  float* As = sm;                 // [KI][BM]
  float* Bs = sm + KI * BM;       // [KI][H]
  __shared__ int s_src[BM];

  int tid = threadIdx.x;
  int bm  = blockIdx.x * BM;
  if (tid < BM) {
    int e = bm + tid;
    s_src[tid] = (e < E) ? esrc[e] : 0;
  }
  __syncthreads();

  for (int i = tid; i < KI * BM; i += 256) {
    int k = i >> 6, m = i & (BM - 1);
    int e = bm + m;
    float v = 0.f;
    if (e < E) v = (k < AF) ? x[(size_t)s_src[m] * AF + k]
                            : bond[(size_t)e * BF + (k - AF)];
    As[k * BM + m] = v;
  }
  for (int i = tid; i < KI * (H / 4); i += 256) {
    int k = i >> 6;
    int h4 = (i & 63) * 4;
    *(float4*)&Bs[k * H + h4] = *(const float4*)&WiT[k * H + h4];
  }
  __syncthreads();

  int tm = tid >> 5, tn = tid & 31;
  float acc[8][8];
#pragma unroll
  for (int i = 0; i < 8; i++)
#pragma unroll
    for (int j = 0; j < 8; j++) acc[i][j] = 0.f;

  for (int k = 0; k < KI; k++) {
    float a[8], b[8];
    *(float4*)(a)     = *(float4*)&As[k * BM + tm * 8];
    *(float4*)(a + 4) = *(float4*)&As[k * BM + tm * 8 + 4];
    *(float4*)(b)     = *(float4*)&Bs[k * H + tn * 8];
    *(float4*)(b + 4) = *(float4*)&Bs[k * H + tn * 8 + 4];
#pragma unroll
    for (int i = 0; i < 8; i++)
#pragma unroll
      for (int j = 0; j < 8; j++)
        acc[i][j] = fmaf(a[i], b[j], acc[i][j]);
  }

#pragma unroll
  for (int i = 0; i < 8; i++) {
    int e = bm + tm * 8 + i;
    if (e >= E) continue;
    size_t base = (size_t)e * H + tn * 8;
    float4 o0, o1, r0, r1;
    o0.x = acc[i][0]; o0.y = acc[i][1]; o0.z = acc[i][2]; o0.w = acc[i][3];
    o1.x = acc[i][4]; o1.y = acc[i][5]; o1.z = acc[i][6]; o1.w = acc[i][7];
    r0.x = fmaxf(o0.x, 0.f); r0.y = fmaxf(o0.y, 0.f); r0.z = fmaxf(o0.z, 0.f); r0.w = fmaxf(o0.w, 0.f);
    r1.x = fmaxf(o1.x, 0.f); r1.y = fmaxf(o1.y, 0.f); r1.z = fmaxf(o1.z, 0.f); r1.w = fmaxf(o1.w, 0.f);
    *(float4*)(msg_input + base)     = o0;
    *(float4*)(msg_input + base + 4) = o1;
    *(float4*)(msg0 + base)          = r0;
    *(float4*)(msg0 + base + 4)      = r1;
  }
}

// ---------------- scatter: S[dst[e]] += msg[e] ------------------------------
__global__ void k_scatter(const float* __restrict__ msg, const int* __restrict__ edst,
                          float* __restrict__ S, int E) {
  int idx = blockIdx.x * blockDim.x + threadIdx.x;
  if (idx >= E * 64) return;
  int e = idx >> 6, q = (idx & 63) * 4;
  float4 v = *(const float4*)(msg + (size_t)e * H + q);
  int d = __ldg(edst + e);
  red_add4(S + (size_t)d * H + q, v.x, v.y, v.z, v.w);
}

// ---------------- message GEMM:
// msg_out[e] = relu(msg_input[e] + (S[src[e]] - msg_cur[rev(e)]) @ W_h^T) -----
__global__ __launch_bounds__(256) void k_msg_gemm(
    const float* __restrict__ S, const float* __restrict__ msg_cur,
    const float* __restrict__ msg_input, const float* __restrict__ WhT,
    const int* __restrict__ esrc, float* __restrict__ msg_out, int E)
{
  __shared__ float As[BK][BM];
  __shared__ float Bs[BK][H];
  __shared__ int s_src[BM];

  int tid = threadIdx.x;
  int bm  = blockIdx.x * BM;
  if (tid < BM) {
    int e = bm + tid;
    s_src[tid] = (e < E) ? esrc[e] : 0;
  }
  __syncthreads();

  int m_l = tid >> 2;          // 0..63 : edge within tile
  int kq  = tid & 3;           // 0..3  : 4 threads cover 16 floats of a row
  int e_m = bm + m_l;
  int eh  = E >> 1;
  int rev = 0;
  if (e_m < E) rev = (e_m < eh) ? (e_m + eh) : (e_m - eh);
  const float* Sp = S       + (size_t)s_src[m_l] * H + kq * 4;
  const float* Rp = msg_cur + (size_t)rev        * H + kq * 4;

  int kb = tid >> 4;                // 0..15 : k row for B load
  int hb = (tid & 15) * 16;         // h offset, 16 floats per thread
  const float* Bg0 = WhT + (size_t)kb * H + hb;

  int tm = tid >> 5, tn = tid & 31;
  float acc[8][8];
#pragma unroll
  for (int i = 0; i < 8; i++)
#pragma unroll
    for (int j = 0; j < 8; j++) acc[i][j] = 0.f;

  for (int kt = 0; kt < H; kt += BK) {
    float4 sv = *(const float4*)(Sp + kt);
    float4 rv = *(const float4*)(Rp + kt);
    const float* Bg = Bg0 + (size_t)kt * H;
    float4 b0 = *(const float4*)(Bg);
    float4 b1 = *(const float4*)(Bg + 4);
    float4 b2 = *(const float4*)(Bg + 8);
    float4 b3 = *(const float4*)(Bg + 12);
    __syncthreads();
    int k0 = kq * 4;
    As[k0 + 0][m_l] = sv.x - rv.x;
    As[k0 + 1][m_l] = sv.y - rv.y;
    As[k0 + 2][m_l] = sv.z - rv.z;
    As[k0 + 3][m_l] = sv.w - rv.w;
    *(float4*)&Bs[kb][hb]      = b0;
    *(float4*)&Bs[kb][hb + 4]  = b1;
    *(float4*)&Bs[kb][hb + 8]  = b2;
    *(float4*)&Bs[kb][hb + 12] = b3;
    __syncthreads();
#pragma unroll
    for (int k = 0; k < BK; k++) {
      float a[8], b[8];
      *(float4*)(a)     = *(float4*)&As[k][tm * 8];
      *(float4*)(a + 4) = *(float4*)&As[k][tm * 8 + 4];
      *(float4*)(b)     = *(float4*)&Bs[k][tn * 8];
      *(float4*)(b + 4) = *(float4*)&Bs[k][tn * 8 + 4];
#pragma unroll
      for (int i = 0; i < 8; i++)
#pragma unroll
        for (int j = 0; j < 8; j++)
          acc[i][j] = fmaf(a[i], b[j], acc[i][j]);
    }
  }

#pragma unroll
  for (int i = 0; i < 8; i++) {
    int e = bm + tm * 8 + i;
    if (e >= E) continue;
    size_t base = (size_t)e * H + tn * 8;
    float4 m0 = *(const float4*)(msg_input + base);
    float4 m1 = *(const float4*)(msg_input + base + 4);
    float4 o0, o1;
    o0.x = fmaxf(acc[i][0] + m0.x, 0.f);
    o0.y = fmaxf(acc[i][1] + m0.y, 0.f);
    o0.z = fmaxf(acc[i][2] + m0.z, 0.f);
    o0.w = fmaxf(acc[i][3] + m0.w, 0.f);
    o1.x = fmaxf(acc[i][4] + m1.x, 0.f);
    o1.y = fmaxf(acc[i][5] + m1.y, 0.f);
    o1.z = fmaxf(acc[i][6] + m1.z, 0.f);
    o1.w = fmaxf(acc[i][7] + m1.w, 0.f);
    *(float4*)(msg_out + base)     = o0;
    *(float4*)(msg_out + base + 4) = o1;
  }
}

// ---------------- output: h = relu(concat(x,S) @ W_o^T + b_o); mol-mean -----
__global__ __launch_bounds__(256) void k_out(
    const float* __restrict__ x, const float* __restrict__ S,
    const float* __restrict__ WoT, const float* __restrict__ b_o,
    float* __restrict__ out, int N, int APM)
{
  __shared__ float As[BK][BM];
  __shared__ float Bs[BK][H];

  int tid = threadIdx.x;
  int bm  = blockIdx.x * BM;
  int m_l = tid >> 2, kq = tid & 3;
  int node = bm + m_l;
  bool nv = node < N;
  int kb = tid >> 4, hb = (tid & 15) * 16;
  int tm = tid >> 5, tn = tid & 31;

  float acc[8][8];
#pragma unroll
  for (int i = 0; i < 8; i++)
#pragma unroll
    for (int j = 0; j < 8; j++) acc[i][j] = 0.f;

  for (int kt = 0; kt < KO_PAD; kt += BK) {
    float av[4];
#pragma unroll
    for (int j = 0; j < 4; j++) {
      int kg = kt + kq * 4 + j;
      float v = 0.f;
      if (nv) {
        if (kg < AF)            v = x[(size_t)node * AF + kg];
        else if (kg < KO_REAL)  v = S[(size_t)node * H + (kg - AF)];
      }
      av[j] = v;
    }
    const float* Bg = WoT + (size_t)(kt + kb) * H + hb;
    float4 b0 = *(const float4*)(Bg);
    float4 b1 = *(const float4*)(Bg + 4);
    float4 b2 = *(const float4*)(Bg + 8);
    float4 b3 = *(const float4*)(Bg + 12);
    __syncthreads();
    int k0 = kq * 4;
    As[k0 + 0][m_l] = av[0];
    As[k0 + 1][m_l] = av[1];
    As[k0 + 2][m_l] = av[2];
    As[k0 + 3][m_l] = av[3];
    *(float4*)&Bs[kb][hb]      = b0;
    *(float4*)&Bs[kb][hb + 4]  = b1;
    *(float4*)&Bs[kb][hb + 8]  = b2;
    *(float4*)&Bs[kb][hb + 12] = b3;
    __syncthreads();
#pragma unroll
    for (int k = 0; k < BK; k++) {
      float a[8], b[8];
      *(float4*)(a)     = *(float4*)&As[k][tm * 8];
      *(float4*)(a + 4) = *(float4*)&As[k][tm * 8 + 4];
      *(float4*)(b)     = *(float4*)&Bs[k][tn * 8];
      *(float4*)(b + 4) = *(float4*)&Bs[k][tn * 8 + 4];
#pragma unroll
      for (int i = 0; i < 8; i++)
#pragma unroll
        for (int j = 0; j < 8; j++)
          acc[i][j] = fmaf(a[i], b[j], acc[i][j]);
    }
  }

  float inv = 1.f / (float)APM;
  float bo[8];
  *(float4*)(bo)     = *(const float4*)(b_o + tn * 8);
  *(float4*)(bo + 4) = *(const float4*)(b_o + tn * 8 + 4);

#pragma unroll
  for (int i = 0; i < 8; i++) {
    int n = bm + tm * 8 + i;
    if (n >= N) continue;
    int mol = n / APM;
    float* op = out + (size_t)mol * H + tn * 8;
    float v[8];
#pragma unroll
    for (int j = 0; j < 8; j++)
      v[j] = fmaxf(acc[i][j] + bo[j], 0.f) * inv;
    red_add4(op,     v[0], v[1], v[2], v[3]);
    red_add4(op + 4, v[4], v[5], v[6], v[7]);
  }
}

// ---------------- host ------------------------------------------------------
extern "C" void kernel_launch(void* const* d_in, const int* in_sizes, int n_in,
                              void* d_out, int out_size) {
  const float* x    = (const float*)d_in[0];
  const float* bond = (const float*)d_in[1];
  const float* W_i  = (const float*)d_in[2];
  const float* W_h  = (const float*)d_in[3];
  const float* W_o  = (const float*)d_in[4];
  const float* b_o  = (const float*)d_in[5];
  const int*   esrc = (const int*)d_in[6];
  const int*   edst = (const int*)d_in[7];
  (void)n_in;

  int N   = in_sizes[0] / AF;
  int E   = in_sizes[1] / BF;
  int NM  = out_size / H;
  int APM = N / NM;

  float *msg_input, *msgA, *msgB, *S, *WiT, *WhT, *WoT;
  cudaGetSymbolAddress((void**)&msg_input, g_msg_input);
  cudaGetSymbolAddress((void**)&msgA, g_msgA);
  cudaGetSymbolAddress((void**)&msgB, g_msgB);
  cudaGetSymbolAddress((void**)&S, g_S);
  cudaGetSymbolAddress((void**)&WiT, g_WiT);
  cudaGetSymbolAddress((void**)&WhT, g_WhT);
  cudaGetSymbolAddress((void**)&WoT, g_WoT);

  // weight transposes (cheap, once per launch)
  k_transpose<<<(KI * H + 255) / 256, 256>>>(WiT, W_i, KI, KI);
  k_transpose<<<(H * H + 255) / 256, 256>>>(WhT, W_h, H, H);
  k_transpose<<<(KO_PAD * H + 255) / 256, 256>>>(WoT, W_o, KO_PAD, KO_REAL);

  // init GEMM
  size_t smem_init = (size_t)(KI * BM + KI * H) * sizeof(float);
  cudaFuncSetAttribute(k_init, cudaFuncAttributeMaxDynamicSharedMemorySize,
                       (int)smem_init);
  int nblk_e = (E + BM - 1) / BM;
  k_init<<<nblk_e, 256, smem_init>>>(x, bond, esrc, WiT, msg_input, msgA, E);

  int sblk = (E * 64 + 255) / 256;
  float* cur = msgA;
  float* nxt = msgB;
  for (int it = 0; it < 5; it++) {
    cudaMemsetAsync(S, 0, (size_t)N * H * sizeof(float));
    k_scatter<<<sblk, 256>>>(cur, edst, S, E);
    k_msg_gemm<<<nblk_e, 256>>>(S, cur, msg_input, WhT, esrc, nxt, E);
    float* t = cur; cur = nxt; nxt = t;
  }

  // final aggregation + output GEMM + mol mean
  cudaMemsetAsync(S, 0, (size_t)N * H * sizeof(float));
  k_scatter<<<sblk, 256>>>(cur, edst, S, E);
  cudaMemsetAsync(d_out, 0, (size_t)out_size * sizeof(float));
  int nblk_n = (N + BM - 1) / BM;
  k_out<<<nblk_n, 256>>>(x, S, WoT, b_o, (float*)d_out, N, APM);
}

// round 3
// speedup vs baseline: 1.0586x; 1.0586x over previous
#include <cuda_runtime.h>
#include <cuda_fp16.h>
#include <cstdint>
#include <cstddef>

#define H        256
#define AF       39
#define BF       11
#define KI       50
#define KO_REAL  295
#define KO_PAD   320
#define EMAX     380000
#define NMAX     200000
#define BM       64
#define LDA      72

// ---------------- scratch (device globals) ----------------------------------
__device__ float g_msg_input[(size_t)EMAX * H];
__device__ float g_msgA[(size_t)EMAX * H];
__device__ float g_msgB[(size_t)EMAX * H];
__device__ float g_S0[(size_t)NMAX * H];
__device__ float g_S1[(size_t)NMAX * H];
__device__ float g_WiT[KI * H];
__device__ __half g_Wh_hi[H * H];
__device__ __half g_Wh_lo[H * H];
__device__ __half g_Wo_hi[H * KO_PAD];
__device__ __half g_Wo_lo[H * KO_PAD];

// ---------------- helpers ----------------------------------------------------
__device__ __forceinline__ void red_add4(float* p, float a, float b, float c, float d) {
  asm volatile("red.global.add.v4.f32 [%0], {%1,%2,%3,%4};"
               :: "l"(p), "f"(a), "f"(b), "f"(c), "f"(d) : "memory");
}
__device__ __forceinline__ void red_add2(float* p, float a, float b) {
  asm volatile("red.global.add.v2.f32 [%0], {%1,%2};"
               :: "l"(p), "f"(a), "f"(b) : "memory");
}
__device__ __forceinline__ uint32_t smem_u32(const void* p) {
  return (uint32_t)__cvta_generic_to_shared(p);
}
__device__ __forceinline__ void ldmA(uint32_t* r, uint32_t addr) {
  asm volatile("ldmatrix.sync.aligned.m8n8.x4.shared.b16 {%0,%1,%2,%3}, [%4];"
               : "=r"(r[0]), "=r"(r[1]), "=r"(r[2]), "=r"(r[3]) : "r"(addr));
}
__device__ __forceinline__ void mma16816(float* c, const uint32_t* a, const uint32_t* b) {
  asm volatile("mma.sync.aligned.m16n8k16.row.col.f32.f16.f16.f32 "
               "{%0,%1,%2,%3}, {%4,%5,%6,%7}, {%8,%9}, {%0,%1,%2,%3};"
               : "+f"(c[0]), "+f"(c[1]), "+f"(c[2]), "+f"(c[3])
               : "r"(a[0]), "r"(a[1]), "r"(a[2]), "r"(a[3]),
                 "r"(b[0]), "r"(b[1]));
}

// ---------------- prep kernels ------------------------------------------------
__global__ void k_transpose(float* __restrict__ dst, const float* __restrict__ src,
                            int Kout, int Kreal) {
  int idx = blockIdx.x * blockDim.x + threadIdx.x;
  if (idx >= Kout * H) return;
  int k = idx >> 8, h = idx & (H - 1);
  dst[idx] = (k < Kreal) ? src[h * Kreal + k] : 0.f;
}

// split fp32 weights into hi/lo fp16, [rows][Kpad] layout from [rows][Kreal]
__global__ void k_split(__half* __restrict__ hi, __half* __restrict__ lo,
                        const float* __restrict__ src, int rows, int Kreal, int Kpad) {
  int idx = blockIdx.x * blockDim.x + threadIdx.x;
  if (idx >= rows * Kpad) return;
  int n = idx / Kpad, k = idx - n * Kpad;
  float v = (k < Kreal) ? src[n * Kreal + k] : 0.f;
  __half h = __float2half_rn(v);
  hi[idx] = h;
  lo[idx] = __float2half_rn(v - __half2float(h));
}

// ---------------- init (SIMT, K=50) + fused scatter into S0 -------------------
__global__ __launch_bounds__(256) void k_init(
    const float* __restrict__ x, const float* __restrict__ bond,
    const int* __restrict__ esrc, const int* __restrict__ edst,
    const float* __restrict__ WiT,
    float* __restrict__ msg_input, float* __restrict__ msg0,
    float* __restrict__ S0, int E)
{
  extern __shared__ float smf[];
  float* As = smf;                // [KI][BM]
  float* Bs = smf + KI * BM;      // [KI][H]
  __shared__ int s_src[BM];

  int tid = threadIdx.x;
  int bm  = blockIdx.x * BM;
  if (tid < BM) {
    int e = bm + tid;
    s_src[tid] = (e < E) ? esrc[e] : 0;
  }
  __syncthreads();

  for (int i = tid; i < KI * BM; i += 256) {
    int k = i >> 6, m = i & (BM - 1);
    int e = bm + m;
    float v = 0.f;
    if (e < E) v = (k < AF) ? x[(size_t)s_src[m] * AF + k]
                            : bond[(size_t)e * BF + (k - AF)];
    As[k * BM + m] = v;
  }
  for (int i = tid; i < KI * (H / 4); i += 256) {
    int k = i >> 6;
    int h4 = (i & 63) * 4;
    *(float4*)&Bs[k * H + h4] = *(const float4*)&WiT[k * H + h4];
  }
  __syncthreads();

  int tm = tid >> 5, tn = tid & 31;
  float acc[8][8];
#pragma unroll
  for (int i = 0; i < 8; i++)
#pragma unroll
    for (int j = 0; j < 8; j++) acc[i][j] = 0.f;

  for (int k = 0; k < KI; k++) {
    float a[8], b[8];
    *(float4*)(a)     = *(float4*)&As[k * BM + tm * 8];
    *(float4*)(a + 4) = *(float4*)&As[k * BM + tm * 8 + 4];
    *(float4*)(b)     = *(float4*)&Bs[k * H + tn * 8];
    *(float4*)(b + 4) = *(float4*)&Bs[k * H + tn * 8 + 4];
#pragma unroll
    for (int i = 0; i < 8; i++)
#pragma unroll
      for (int j = 0; j < 8; j++)
        acc[i][j] = fmaf(a[i], b[j], acc[i][j]);
  }

#pragma unroll
  for (int i = 0; i < 8; i++) {
    int e = bm + tm * 8 + i;
    if (e >= E) continue;
    int d = edst[e];
    size_t base = (size_t)e * H + tn * 8;
    float4 o0, o1, r0, r1;
    o0.x = acc[i][0]; o0.y = acc[i][1]; o0.z = acc[i][2]; o0.w = acc[i][3];
    o1.x = acc[i][4]; o1.y = acc[i][5]; o1.z = acc[i][6]; o1.w = acc[i][7];
    r0.x = fmaxf(o0.x, 0.f); r0.y = fmaxf(o0.y, 0.f); r0.z = fmaxf(o0.z, 0.f); r0.w = fmaxf(o0.w, 0.f);
    r1.x = fmaxf(o1.x, 0.f); r1.y = fmaxf(o1.y, 0.f); r1.z = fmaxf(o1.z, 0.f); r1.w = fmaxf(o1.w, 0.f);
    *(float4*)(msg_input + base)     = o0;
    *(float4*)(msg_input + base + 4) = o1;
    *(float4*)(msg0 + base)          = r0;
    *(float4*)(msg0 + base + 4)      = r1;
    float* sp = S0 + (size_t)d * H + tn * 8;
    red_add4(sp,     r0.x, r0.y, r0.z, r0.w);
    red_add4(sp + 4, r1.x, r1.y, r1.z, r1.w);
  }
}

// ---------------- message GEMM via mma.sync fp16x3 ---------------------------
// msg_out[e] = relu(msg_input[e] + (S[src[e]] - msg_cur[rev(e)]) @ W_h^T)
// epilogue scatters msg_out into Snext[dst[e]].
__global__ __launch_bounds__(256, 1) void k_msg(
    const float* __restrict__ S, const float* __restrict__ msg_cur,
    const float* __restrict__ msg_input,
    const __half* __restrict__ Wh_hi, const __half* __restrict__ Wh_lo,
    const int* __restrict__ esrc, const int* __restrict__ edst,
    float* __restrict__ msg_out, float* __restrict__ Snext, int E)
{
  __shared__ __align__(16) __half Ahi[64 * LDA];
  __shared__ __align__(16) __half Alo[64 * LDA];

  int tid = threadIdx.x;
  int wid = tid >> 5, lane = tid & 31;
  int wm = wid & 1, wn = wid >> 1;
  int gid = lane >> 2, tig = lane & 3;
  int bm = blockIdx.x * 64;

  // staging mapping: 4 threads per row, 16 k each
  int srow = tid >> 2;
  int skq  = (tid & 3) * 16;
  int e = bm + srow;
  bool ev = e < E;
  int eh = E >> 1;
  int sidx = 0, ridx = 0;
  if (ev) { sidx = __ldg(esrc + e); ridx = (e < eh) ? (e + eh) : (e - eh); }
  const float* Sp = S       + (size_t)sidx * H;
  const float* Rp = msg_cur + (size_t)ridx * H;

  const __half* BH = Wh_hi + (size_t)(wn * 64 + gid) * H + tig * 2;
  const __half* BL = Wh_lo + (size_t)(wn * 64 + gid) * H + tig * 2;

  float acc[2][8][4];
#pragma unroll
  for (int mi = 0; mi < 2; mi++)
#pragma unroll
    for (int ni = 0; ni < 8; ni++)
#pragma unroll
      for (int q = 0; q < 4; q++) acc[mi][ni][q] = 0.f;

  uint32_t ahi_b = smem_u32(Ahi);
  uint32_t alo_b = smem_u32(Alo);
  // ldmatrix address pieces (per thread)
  int lrow = (lane & 7) + ((lane >> 3) & 1) * 8;
  int lcol = (lane >> 4) * 8;

  for (int kc = 0; kc < 4; kc++) {
    __syncthreads();
    {
      float a[16];
      if (ev) {
#pragma unroll
        for (int q = 0; q < 4; q++) {
          float4 sv = *(const float4*)(Sp + kc * 64 + skq + q * 4);
          float4 rv = *(const float4*)(Rp + kc * 64 + skq + q * 4);
          a[q * 4 + 0] = sv.x - rv.x; a[q * 4 + 1] = sv.y - rv.y;
          a[q * 4 + 2] = sv.z - rv.z; a[q * 4 + 3] = sv.w - rv.w;
        }
      } else {
#pragma unroll
        for (int j = 0; j < 16; j++) a[j] = 0.f;
      }
      __half hh[16], ll[16];
#pragma unroll
      for (int j = 0; j < 16; j++) {
        __half h = __float2half_rn(a[j]);
        hh[j] = h;
        ll[j] = __float2half_rn(a[j] - __half2float(h));
      }
      *(uint4*)&Ahi[srow * LDA + skq]     = *(uint4*)&hh[0];
      *(uint4*)&Ahi[srow * LDA + skq + 8] = *(uint4*)&hh[8];
      *(uint4*)&Alo[srow * LDA + skq]     = *(uint4*)&ll[0];
      *(uint4*)&Alo[srow * LDA + skq + 8] = *(uint4*)&ll[8];
    }
    __syncthreads();

#pragma unroll
    for (int ks = 0; ks < 4; ks++) {
      uint32_t a_hi[2][4], a_lo[2][4];
#pragma unroll
      for (int mi = 0; mi < 2; mi++) {
        int rowg = wm * 32 + mi * 16 + lrow;
        int colg = ks * 16 + lcol;
        uint32_t off = (uint32_t)(rowg * LDA + colg) * 2;
        ldmA(a_hi[mi], ahi_b + off);
        ldmA(a_lo[mi], alo_b + off);
      }
#pragma unroll
      for (int ni = 0; ni < 8; ni++) {
        size_t boff = (size_t)ni * 8 * H + kc * 64 + ks * 16;
        uint32_t bh[2], bl[2];
        bh[0] = *(const uint32_t*)(BH + boff);
        bh[1] = *(const uint32_t*)(BH + boff + 8);
        bl[0] = *(const uint32_t*)(BL + boff);
        bl[1] = *(const uint32_t*)(BL + boff + 8);
#pragma unroll
        for (int mi = 0; mi < 2; mi++) {
          mma16816(acc[mi][ni], a_hi[mi], bh);
          mma16816(acc[mi][ni], a_hi[mi], bl);
          mma16816(acc[mi][ni], a_lo[mi], bh);
        }
      }
    }
  }

  // epilogue: +msg_input, relu, store, scatter
#pragma unroll
  for (int mi = 0; mi < 2; mi++) {
    int r0 = bm + wm * 32 + mi * 16 + gid;
    int r1 = r0 + 8;
    bool v0 = r0 < E, v1 = r1 < E;
    int d0 = v0 ? __ldg(edst + r0) : 0;
    int d1 = v1 ? __ldg(edst + r1) : 0;
    const float* MI0 = msg_input + (size_t)r0 * H;
    const float* MI1 = msg_input + (size_t)r1 * H;
    float* MO0 = msg_out + (size_t)r0 * H;
    float* MO1 = msg_out + (size_t)r1 * H;
    float* SN0 = Snext + (size_t)d0 * H;
    float* SN1 = Snext + (size_t)d1 * H;
#pragma unroll
    for (int ni = 0; ni < 8; ni++) {
      int n = wn * 64 + ni * 8 + tig * 2;
      if (v0) {
        float2 m0 = *(const float2*)(MI0 + n);
        float o0 = fmaxf(acc[mi][ni][0] + m0.x, 0.f);
        float o1 = fmaxf(acc[mi][ni][1] + m0.y, 0.f);
        float2 o = {o0, o1};
        *(float2*)(MO0 + n) = o;
        red_add2(SN0 + n, o0, o1);
      }
      if (v1) {
        float2 m1 = *(const float2*)(MI1 + n);
        float o2 = fmaxf(acc[mi][ni][2] + m1.x, 0.f);
        float o3 = fmaxf(acc[mi][ni][3] + m1.y, 0.f);
        float2 o = {o2, o3};
        *(float2*)(MO1 + n) = o;
        red_add2(SN1 + n, o2, o3);
      }
    }
  }
}

// ---------------- output GEMM via mma.sync fp16x3 ----------------------------
// h = relu(concat(x[n], S[n]) @ W_o^T + b_o); out[mol] += h / APM
__global__ __launch_bounds__(256, 1) void k_out(
    const float* __restrict__ x, const float* __restrict__ S,
    const __half* __restrict__ Wo_hi, const __half* __restrict__ Wo_lo,
    const float* __restrict__ b_o, float* __restrict__ out,
    int N, int APM)
{
  __shared__ __align__(16) __half Ahi[64 * LDA];
  __shared__ __align__(16) __half Alo[64 * LDA];

  int tid = threadIdx.x;
  int wid = tid >> 5, lane = tid & 31;
  int wm = wid & 1, wn = wid >> 1;
  int gid = lane >> 2, tig = lane & 3;
  int bm = blockIdx.x * 64;

  int srow = tid >> 2;
  int skq  = (tid & 3) * 16;
  int node = bm + srow;
  bool nv = node < N;
  const float* Xp = x + (size_t)node * AF;
  const float* Sp = S + (size_t)node * H;

  const __half* BH = Wo_hi + (size_t)(wn * 64 + gid) * KO_PAD + tig * 2;
  const __half* BL = Wo_lo + (size_t)(wn * 64 + gid) * KO_PAD + tig * 2;

  float acc[2][8][4];
#pragma unroll
  for (int mi = 0; mi < 2; mi++)
#pragma unroll
    for (int ni = 0; ni < 8; ni++)
#pragma unroll
      for (int q = 0; q < 4; q++) acc[mi][ni][q] = 0.f;

  uint32_t ahi_b = smem_u32(Ahi);
  uint32_t alo_b = smem_u32(Alo);
  int lrow = (lane & 7) + ((lane >> 3) & 1) * 8;
  int lcol = (lane >> 4) * 8;

  for (int kc = 0; kc < 5; kc++) {
    __syncthreads();
    {
      __half hh[16], ll[16];
#pragma unroll
      for (int j = 0; j < 16; j++) {
        int kg = kc * 64 + skq + j;
        float a = 0.f;
        if (nv) {
          if (kg < AF)           a = Xp[kg];
          else if (kg < KO_REAL) a = Sp[kg - AF];
        }
        __half h = __float2half_rn(a);
        hh[j] = h;
        ll[j] = __float2half_rn(a - __half2float(h));
      }
      *(uint4*)&Ahi[srow * LDA + skq]     = *(uint4*)&hh[0];
      *(uint4*)&Ahi[srow * LDA + skq + 8] = *(uint4*)&hh[8];
      *(uint4*)&Alo[srow * LDA + skq]     = *(uint4*)&ll[0];
      *(uint4*)&Alo[srow * LDA + skq + 8] = *(uint4*)&ll[8];
    }
    __syncthreads();

#pragma unroll
    for (int ks = 0; ks < 4; ks++) {
      uint32_t a_hi[2][4], a_lo[2][4];
#pragma unroll
      for (int mi = 0; mi < 2; mi++) {
        int rowg = wm * 32 + mi * 16 + lrow;
        int colg = ks * 16 + lcol;
        uint32_t off = (uint32_t)(rowg * LDA + colg) * 2;
        ldmA(a_hi[mi], ahi_b + off);
        ldmA(a_lo[mi], alo_b + off);
      }
#pragma unroll
      for (int ni = 0; ni < 8; ni++) {
        size_t boff = (size_t)ni * 8 * KO_PAD + kc * 64 + ks * 16;
        uint32_t bh[2], bl[2];
        bh[0] = *(const uint32_t*)(BH + boff);
        bh[1] = *(const uint32_t*)(BH + boff + 8);
        bl[0] = *(const uint32_t*)(BL + boff);
        bl[1] = *(const uint32_t*)(BL + boff + 8);
#pragma unroll
        for (int mi = 0; mi < 2; mi++) {
          mma16816(acc[mi][ni], a_hi[mi], bh);
          mma16816(acc[mi][ni], a_hi[mi], bl);
          mma16816(acc[mi][ni], a_lo[mi], bh);
        }
      }
    }
  }

  float inv = 1.f / (float)APM;
#pragma unroll
  for (int mi = 0; mi < 2; mi++) {
    int r0 = bm + wm * 32 + mi * 16 + gid;
    int r1 = r0 + 8;
    bool v0 = r0 < N, v1 = r1 < N;
    int mol0 = v0 ? (r0 / APM) : 0;
    int mol1 = v1 ? (r1 / APM) : 0;
    float* O0 = out + (size_t)mol0 * H;
    float* O1 = out + (size_t)mol1 * H;
#pragma unroll
    for (int ni = 0; ni < 8; ni++) {
      int n = wn * 64 + ni * 8 + tig * 2;
      float2 bo = *(const float2*)(b_o + n);
      if (v0) {
        float o0 = fmaxf(acc[mi][ni][0] + bo.x, 0.f) * inv;
        float o1 = fmaxf(acc[mi][ni][1] + bo.y, 0.f) * inv;
        red_add2(O0 + n, o0, o1);
      }
      if (v1) {
        float o2 = fmaxf(acc[mi][ni][2] + bo.x, 0.f) * inv;
        float o3 = fmaxf(acc[mi][ni][3] + bo.y, 0.f) * inv;
        red_add2(O1 + n, o2, o3);
      }
    }
  }
}

// ---------------- host ---------------------------------------------------------
extern "C" void kernel_launch(void* const* d_in, const int* in_sizes, int n_in,
                              void* d_out, int out_size) {
  const float* x    = (const float*)d_in[0];
  const float* bond = (const float*)d_in[1];
  const float* W_i  = (const float*)d_in[2];
  const float* W_h  = (const float*)d_in[3];
  const float* W_o  = (const float*)d_in[4];
  const float* b_o  = (const float*)d_in[5];
  const int*   esrc = (const int*)d_in[6];
  const int*   edst = (const int*)d_in[7];
  (void)n_in;

  int N   = in_sizes[0] / AF;
  int E   = in_sizes[1] / BF;
  int NM  = out_size / H;
  int APM = N / NM;

  float *msg_input, *msgA, *msgB, *S0, *S1, *WiT;
  __half *WhH, *WhL, *WoH, *WoL;
  cudaGetSymbolAddress((void**)&msg_input, g_msg_input);
  cudaGetSymbolAddress((void**)&msgA, g_msgA);
  cudaGetSymbolAddress((void**)&msgB, g_msgB);
  cudaGetSymbolAddress((void**)&S0, g_S0);
  cudaGetSymbolAddress((void**)&S1, g_S1);
  cudaGetSymbolAddress((void**)&WiT, g_WiT);
  cudaGetSymbolAddress((void**)&WhH, g_Wh_hi);
  cudaGetSymbolAddress((void**)&WhL, g_Wh_lo);
  cudaGetSymbolAddress((void**)&WoH, g_Wo_hi);
  cudaGetSymbolAddress((void**)&WoL, g_Wo_lo);

  // prep
  k_transpose<<<(KI * H + 255) / 256, 256>>>(WiT, W_i, KI, KI);
  k_split<<<(H * H + 255) / 256, 256>>>(WhH, WhL, W_h, H, H, H);
  k_split<<<(H * KO_PAD + 255) / 256, 256>>>(WoH, WoL, W_o, H, KO_REAL, KO_PAD);

  size_t smem_init = (size_t)(KI * BM + KI * H) * sizeof(float);
  cudaFuncSetAttribute(k_init, cudaFuncAttributeMaxDynamicSharedMemorySize, (int)smem_init);

  // init + scatter into S0
  cudaMemsetAsync(S0, 0, (size_t)N * H * sizeof(float));
  int nblk_i = (E + BM - 1) / BM;
  k_init<<<nblk_i, 256, smem_init>>>(x, bond, esrc, edst, WiT, msg_input, msgA, S0, E);

  int nblk_e = (E + 63) / 64;
  float* cur = msgA; float* nxt = msgB;
  float* Scur = S0;  float* Snext = S1;
  for (int it = 0; it < 5; it++) {
    cudaMemsetAsync(Snext, 0, (size_t)N * H * sizeof(float));
    k_msg<<<nblk_e, 256>>>(Scur, cur, msg_input, WhH, WhL, esrc, edst, nxt, Snext, E);
    float* t = cur; cur = nxt; nxt = t;
    t = Scur; Scur = Snext; Snext = t;
  }

  cudaMemsetAsync(d_out, 0, (size_t)out_size * sizeof(float));
  int nblk_n = (N + 63) / 64;
  k_out<<<nblk_n, 256>>>(x, Scur, WoH, WoL, b_o, (float*)d_out, N, APM);
}

// round 4
// speedup vs baseline: 1.7375x; 1.6413x over previous
#include <cuda_runtime.h>
#include <cuda_fp16.h>
#include <cstdint>
#include <cstddef>

#define H        256
#define AF       39
#define BF       11
#define KI       50
#define KO_REAL  295
#define KO_PAD   320
#define EMAX     380000
#define NMAX     200000
#define BM       64
#define LDA2     40            // 32 k + 8 pad (halves)

// smem byte offsets (per-stage A: 64*40*2 = 5120B; B: 256*40*2 = 20480B)
#define OFF_AH(b)  ((b) * 10240)
#define OFF_AL(b)  ((b) * 10240 + 5120)
#define OFF_BH(b)  (20480 + (b) * 40960)
#define OFF_BL(b)  (20480 + (b) * 40960 + 20480)
#define SMEM_TC    102400

// ---------------- scratch (device globals) ----------------------------------
__device__ float g_msg_input[(size_t)EMAX * H];
__device__ float g_msgA[(size_t)EMAX * H];
__device__ float g_msgB[(size_t)EMAX * H];
__device__ float g_S0[(size_t)NMAX * H];
__device__ float g_S1[(size_t)NMAX * H];
__device__ float g_WiT[KI * H];
__device__ __half g_Wh_hi[H * H];
__device__ __half g_Wh_lo[H * H];
__device__ __half g_Wo_hi[H * KO_PAD];
__device__ __half g_Wo_lo[H * KO_PAD];

// ---------------- helpers ----------------------------------------------------
__device__ __forceinline__ void red_add4(float* p, float a, float b, float c, float d) {
  asm volatile("red.global.add.v4.f32 [%0], {%1,%2,%3,%4};"
               :: "l"(p), "f"(a), "f"(b), "f"(c), "f"(d) : "memory");
}
__device__ __forceinline__ void red_add2(float* p, float a, float b) {
  asm volatile("red.global.add.v2.f32 [%0], {%1,%2};"
               :: "l"(p), "f"(a), "f"(b) : "memory");
}
__device__ __forceinline__ uint32_t smem_u32(const void* p) {
  return (uint32_t)__cvta_generic_to_shared(p);
}
__device__ __forceinline__ void ldmA(uint32_t* r, uint32_t addr) {
  asm volatile("ldmatrix.sync.aligned.m8n8.x4.shared.b16 {%0,%1,%2,%3}, [%4];"
               : "=r"(r[0]), "=r"(r[1]), "=r"(r[2]), "=r"(r[3]) : "r"(addr));
}
__device__ __forceinline__ uint32_t lds32(uint32_t a) {
  uint32_t r;
  asm("ld.shared.b32 %0, [%1];" : "=r"(r) : "r"(a));
  return r;
}
__device__ __forceinline__ void mma16816(float* c, const uint32_t* a, const uint32_t* b) {
  asm volatile("mma.sync.aligned.m16n8k16.row.col.f32.f16.f16.f32 "
               "{%0,%1,%2,%3}, {%4,%5,%6,%7}, {%8,%9}, {%0,%1,%2,%3};"
               : "+f"(c[0]), "+f"(c[1]), "+f"(c[2]), "+f"(c[3])
               : "r"(a[0]), "r"(a[1]), "r"(a[2]), "r"(a[3]),
                 "r"(b[0]), "r"(b[1]));
}
#define CP16(dst, src) \
  asm volatile("cp.async.cg.shared.global [%0], [%1], 16;" :: "r"(dst), "l"(src))
#define CP_COMMIT() asm volatile("cp.async.commit_group;" ::: "memory")
#define CP_WAIT(n)  asm volatile("cp.async.wait_group %0;" :: "n"(n) : "memory")

// ---------------- fused prep (single launch) ---------------------------------
__global__ void k_prep(float* __restrict__ WiT, const float* __restrict__ W_i,
                       __half* __restrict__ WhH, __half* __restrict__ WhL,
                       const float* __restrict__ W_h,
                       __half* __restrict__ WoH, __half* __restrict__ WoL,
                       const float* __restrict__ W_o) {
  int idx = blockIdx.x * 256 + threadIdx.x;
  if (idx < KI * H) {
    int k = idx >> 8, h = idx & (H - 1);
    WiT[idx] = W_i[h * KI + k];
  }
  if (idx < H * H) {
    float v = W_h[idx];
    __half hh = __float2half_rn(v);
    WhH[idx] = hh;
    WhL[idx] = __float2half_rn(v - __half2float(hh));
  }
  if (idx < H * KO_PAD) {
    int n = idx / KO_PAD, k = idx - n * KO_PAD;
    float v = (k < KO_REAL) ? W_o[n * KO_REAL + k] : 0.f;
    __half hh = __float2half_rn(v);
    WoH[idx] = hh;
    WoL[idx] = __float2half_rn(v - __half2float(hh));
  }
}

// ---------------- init (SIMT, K=50) + fused scatter into S0 -------------------
__global__ __launch_bounds__(256) void k_init(
    const float* __restrict__ x, const float* __restrict__ bond,
    const int* __restrict__ esrc, const int* __restrict__ edst,
    const float* __restrict__ WiT,
    float* __restrict__ msg_input, float* __restrict__ msg0,
    float* __restrict__ S0, int E)
{
  extern __shared__ float smf[];
  float* As = smf;                // [KI][BM]
  float* Bs = smf + KI * BM;      // [KI][H]
  __shared__ int s_src[BM];

  int tid = threadIdx.x;
  int bm  = blockIdx.x * BM;
  if (tid < BM) {
    int e = bm + tid;
    s_src[tid] = (e < E) ? esrc[e] : 0;
  }
  __syncthreads();

  for (int i = tid; i < KI * BM; i += 256) {
    int k = i >> 6, m = i & (BM - 1);
    int e = bm + m;
    float v = 0.f;
    if (e < E) v = (k < AF) ? x[(size_t)s_src[m] * AF + k]
                            : bond[(size_t)e * BF + (k - AF)];
    As[k * BM + m] = v;
  }
  for (int i = tid; i < KI * (H / 4); i += 256) {
    int k = i >> 6;
    int h4 = (i & 63) * 4;
    *(float4*)&Bs[k * H + h4] = *(const float4*)&WiT[k * H + h4];
  }
  __syncthreads();

  int tm = tid >> 5, tn = tid & 31;
  float acc[8][8];
#pragma unroll
  for (int i = 0; i < 8; i++)
#pragma unroll
    for (int j = 0; j < 8; j++) acc[i][j] = 0.f;

  for (int k = 0; k < KI; k++) {
    float a[8], b[8];
    *(float4*)(a)     = *(float4*)&As[k * BM + tm * 8];
    *(float4*)(a + 4) = *(float4*)&As[k * BM + tm * 8 + 4];
    *(float4*)(b)     = *(float4*)&Bs[k * H + tn * 8];
    *(float4*)(b + 4) = *(float4*)&Bs[k * H + tn * 8 + 4];
#pragma unroll
    for (int i = 0; i < 8; i++)
#pragma unroll
      for (int j = 0; j < 8; j++)
        acc[i][j] = fmaf(a[i], b[j], acc[i][j]);
  }

#pragma unroll
  for (int i = 0; i < 8; i++) {
    int e = bm + tm * 8 + i;
    if (e >= E) continue;
    int d = edst[e];
    size_t base = (size_t)e * H + tn * 8;
    float4 o0, o1, r0, r1;
    o0.x = acc[i][0]; o0.y = acc[i][1]; o0.z = acc[i][2]; o0.w = acc[i][3];
    o1.x = acc[i][4]; o1.y = acc[i][5]; o1.z = acc[i][6]; o1.w = acc[i][7];
    r0.x = fmaxf(o0.x, 0.f); r0.y = fmaxf(o0.y, 0.f); r0.z = fmaxf(o0.z, 0.f); r0.w = fmaxf(o0.w, 0.f);
    r1.x = fmaxf(o1.x, 0.f); r1.y = fmaxf(o1.y, 0.f); r1.z = fmaxf(o1.z, 0.f); r1.w = fmaxf(o1.w, 0.f);
    *(float4*)(msg_input + base)     = o0;
    *(float4*)(msg_input + base + 4) = o1;
    *(float4*)(msg0 + base)          = r0;
    *(float4*)(msg0 + base + 4)      = r1;
    float* sp = S0 + (size_t)d * H + tn * 8;
    red_add4(sp,     r0.x, r0.y, r0.z, r0.w);
    red_add4(sp + 4, r1.x, r1.y, r1.z, r1.w);
  }
}

// ---------------- message GEMM: pipelined smem-B fp16x3 mma ------------------
__global__ __launch_bounds__(256, 2) void k_msg(
    const float* __restrict__ S, const float* __restrict__ msg_cur,
    const float* __restrict__ msg_input,
    const __half* __restrict__ Wh_hi, const __half* __restrict__ Wh_lo,
    const int* __restrict__ esrc, const int* __restrict__ edst,
    float* __restrict__ msg_out, float* __restrict__ Snext, int E)
{
  extern __shared__ __align__(16) char smc[];
  uint32_t sb = smem_u32(smc);
  int tid = threadIdx.x, wid = tid >> 5, lane = tid & 31;
  int wm = wid & 1, wn = wid >> 1;
  int gid = lane >> 2, tig = lane & 3;
  int bm = blockIdx.x * 64;

  int srow = tid >> 2;
  int skq  = (tid & 3) * 8;   // 8 floats per thread per chunk
  int e = bm + srow;
  bool ev = e < E;
  int eh = E >> 1;
  int sidx = 0, ridx = 0;
  if (ev) { sidx = __ldg(esrc + e); ridx = (e < eh) ? (e + eh) : (e - eh); }
  const float* Sp = S       + (size_t)sidx * H + skq;
  const float* Rp = msg_cur + (size_t)ridx * H + skq;

  const char* WHp = (const char*)(Wh_hi + (size_t)tid * H);
  const char* WLp = (const char*)(Wh_lo + (size_t)tid * H);
  uint32_t aStoreOff = (uint32_t)(srow * 80 + skq * 2);
  uint32_t bDstOff   = (uint32_t)(tid * 80);

  int lrow = (lane & 7) + ((lane >> 3) & 1) * 8;
  int lcol = (lane >> 4) * 8;

  float acc[2][8][4];
#pragma unroll
  for (int mi = 0; mi < 2; mi++)
#pragma unroll
    for (int ni = 0; ni < 8; ni++)
#pragma unroll
      for (int q = 0; q < 4; q++) acc[mi][ni][q] = 0.f;

  float4 ga0, ga1, gr0, gr1;

  // --- helpers as lambdas ---
  auto cpB = [&](int kc, int buf) {
    const char* sh = WHp + kc * 64;
    const char* sl = WLp + kc * 64;
    uint32_t dh = sb + OFF_BH(buf) + bDstOff;
    uint32_t dl = sb + OFF_BL(buf) + bDstOff;
#pragma unroll
    for (int i = 0; i < 4; i++) CP16(dh + i * 16, sh + i * 16);
#pragma unroll
    for (int i = 0; i < 4; i++) CP16(dl + i * 16, sl + i * 16);
    CP_COMMIT();
  };
  auto gatherA = [&](int kc) {
    if (ev) {
      ga0 = *(const float4*)(Sp + kc * 32);
      ga1 = *(const float4*)(Sp + kc * 32 + 4);
      gr0 = *(const float4*)(Rp + kc * 32);
      gr1 = *(const float4*)(Rp + kc * 32 + 4);
    } else {
      ga0 = ga1 = gr0 = gr1 = make_float4(0.f, 0.f, 0.f, 0.f);
    }
  };
  auto storeA = [&](int buf) {
    float a[8];
    a[0] = ga0.x - gr0.x; a[1] = ga0.y - gr0.y; a[2] = ga0.z - gr0.z; a[3] = ga0.w - gr0.w;
    a[4] = ga1.x - gr1.x; a[5] = ga1.y - gr1.y; a[6] = ga1.z - gr1.z; a[7] = ga1.w - gr1.w;
    __half hh[8], ll[8];
#pragma unroll
    for (int j = 0; j < 8; j++) {
      __half h = __float2half_rn(a[j]);
      hh[j] = h;
      ll[j] = __float2half_rn(a[j] - __half2float(h));
    }
    *(uint4*)(smc + OFF_AH(buf) + aStoreOff) = *(uint4*)hh;
    *(uint4*)(smc + OFF_AL(buf) + aStoreOff) = *(uint4*)ll;
  };

  // --- prologue ---
  cpB(0, 0);
  gatherA(0);
  cpB(1, 1);
  storeA(0);
  gatherA(1);
  CP_WAIT(1);
  __syncthreads();

  // --- main loop over 8 k-chunks of 32 ---
#pragma unroll 1
  for (int kc = 0; kc < 8; kc++) {
    int cur = kc & 1;
    uint32_t aH = sb + OFF_AH(cur), aL = sb + OFF_AL(cur);
    uint32_t bH = sb + OFF_BH(cur), bL = sb + OFF_BL(cur);
#pragma unroll
    for (int ks = 0; ks < 2; ks++) {
      uint32_t a_hi[2][4], a_lo[2][4];
#pragma unroll
      for (int mi = 0; mi < 2; mi++) {
        uint32_t off = (uint32_t)((wm * 32 + mi * 16 + lrow) * LDA2 + ks * 16 + lcol) * 2;
        ldmA(a_hi[mi], aH + off);
        ldmA(a_lo[mi], aL + off);
      }
#pragma unroll
      for (int ni = 0; ni < 8; ni++) {
        uint32_t bo = (uint32_t)((wn * 64 + ni * 8 + gid) * LDA2 + ks * 16 + tig * 2) * 2;
        uint32_t bh[2], bl[2];
        bh[0] = lds32(bH + bo); bh[1] = lds32(bH + bo + 16);
        bl[0] = lds32(bL + bo); bl[1] = lds32(bL + bo + 16);
#pragma unroll
        for (int mi = 0; mi < 2; mi++) {
          mma16816(acc[mi][ni], a_hi[mi], bh);
          mma16816(acc[mi][ni], a_hi[mi], bl);
          mma16816(acc[mi][ni], a_lo[mi], bh);
        }
      }
    }
    if (kc < 7) storeA(cur ^ 1);
    CP_WAIT(0);
    __syncthreads();
    if (kc < 6) { cpB(kc + 2, cur); gatherA(kc + 2); }
  }

  // --- epilogue: +msg_input, relu, store, scatter ---
#pragma unroll
  for (int mi = 0; mi < 2; mi++) {
    int r0 = bm + wm * 32 + mi * 16 + gid;
    int r1 = r0 + 8;
    bool v0 = r0 < E, v1 = r1 < E;
    int d0 = v0 ? __ldg(edst + r0) : 0;
    int d1 = v1 ? __ldg(edst + r1) : 0;
    const float* MI0 = msg_input + (size_t)r0 * H;
    const float* MI1 = msg_input + (size_t)r1 * H;
    float* MO0 = msg_out + (size_t)r0 * H;
    float* MO1 = msg_out + (size_t)r1 * H;
    float* SN0 = Snext + (size_t)d0 * H;
    float* SN1 = Snext + (size_t)d1 * H;
#pragma unroll
    for (int ni = 0; ni < 8; ni++) {
      int n = wn * 64 + ni * 8 + tig * 2;
      if (v0) {
        float2 m0 = *(const float2*)(MI0 + n);
        float o0 = fmaxf(acc[mi][ni][0] + m0.x, 0.f);
        float o1 = fmaxf(acc[mi][ni][1] + m0.y, 0.f);
        float2 o = {o0, o1};
        *(float2*)(MO0 + n) = o;
        red_add2(SN0 + n, o0, o1);
      }
      if (v1) {
        float2 m1 = *(const float2*)(MI1 + n);
        float o2 = fmaxf(acc[mi][ni][2] + m1.x, 0.f);
        float o3 = fmaxf(acc[mi][ni][3] + m1.y, 0.f);
        float2 o = {o2, o3};
        *(float2*)(MO1 + n) = o;
        red_add2(SN1 + n, o2, o3);
      }
    }
  }
}

// ---------------- output GEMM: pipelined smem-B fp16x3 mma -------------------
__global__ __launch_bounds__(256, 2) void k_out(
    const float* __restrict__ x, const float* __restrict__ S,
    const __half* __restrict__ Wo_hi, const __half* __restrict__ Wo_lo,
    const float* __restrict__ b_o, float* __restrict__ out,
    int N, int APM)
{
  extern __shared__ __align__(16) char smc[];
  uint32_t sb = smem_u32(smc);
  int tid = threadIdx.x, wid = tid >> 5, lane = tid & 31;
  int wm = wid & 1, wn = wid >> 1;
  int gid = lane >> 2, tig = lane & 3;
  int bm = blockIdx.x * 64;

  int srow = tid >> 2;
  int skq  = (tid & 3) * 8;
  int node = bm + srow;
  bool nv = node < N;
  const float* Xp = x + (size_t)node * AF;
  const float* Sp = S + (size_t)node * H;

  const char* WHp = (const char*)(Wo_hi + (size_t)tid * KO_PAD);
  const char* WLp = (const char*)(Wo_lo + (size_t)tid * KO_PAD);
  uint32_t aStoreOff = (uint32_t)(srow * 80 + skq * 2);
  uint32_t bDstOff   = (uint32_t)(tid * 80);

  int lrow = (lane & 7) + ((lane >> 3) & 1) * 8;
  int lcol = (lane >> 4) * 8;

  float acc[2][8][4];
#pragma unroll
  for (int mi = 0; mi < 2; mi++)
#pragma unroll
    for (int ni = 0; ni < 8; ni++)
#pragma unroll
      for (int q = 0; q < 4; q++) acc[mi][ni][q] = 0.f;

  float ga[8];

  auto cpB = [&](int kc, int buf) {
    const char* sh = WHp + kc * 64;
    const char* sl = WLp + kc * 64;
    uint32_t dh = sb + OFF_BH(buf) + bDstOff;
    uint32_t dl = sb + OFF_BL(buf) + bDstOff;
#pragma unroll
    for (int i = 0; i < 4; i++) CP16(dh + i * 16, sh + i * 16);
#pragma unroll
    for (int i = 0; i < 4; i++) CP16(dl + i * 16, sl + i * 16);
    CP_COMMIT();
  };
  auto gatherA = [&](int kc) {
#pragma unroll
    for (int j = 0; j < 8; j++) {
      int kg = kc * 32 + skq + j;
      float v = 0.f;
      if (nv) {
        if (kg < AF)           v = Xp[kg];
        else if (kg < KO_REAL) v = Sp[kg - AF];
      }
      ga[j] = v;
    }
  };
  auto storeA = [&](int buf) {
    __half hh[8], ll[8];
#pragma unroll
    for (int j = 0; j < 8; j++) {
      __half h = __float2half_rn(ga[j]);
      hh[j] = h;
      ll[j] = __float2half_rn(ga[j] - __half2float(h));
    }
    *(uint4*)(smc + OFF_AH(buf) + aStoreOff) = *(uint4*)hh;
    *(uint4*)(smc + OFF_AL(buf) + aStoreOff) = *(uint4*)ll;
  };

  cpB(0, 0);
  gatherA(0);
  cpB(1, 1);
  storeA(0);
  gatherA(1);
  CP_WAIT(1);
  __syncthreads();

#pragma unroll 1
  for (int kc = 0; kc < 10; kc++) {
    int cur = kc & 1;
    uint32_t aH = sb + OFF_AH(cur), aL = sb + OFF_AL(cur);
    uint32_t bH = sb + OFF_BH(cur), bL = sb + OFF_BL(cur);
#pragma unroll
    for (int ks = 0; ks < 2; ks++) {
      uint32_t a_hi[2][4], a_lo[2][4];
#pragma unroll
      for (int mi = 0; mi < 2; mi++) {
        uint32_t off = (uint32_t)((wm * 32 + mi * 16 + lrow) * LDA2 + ks * 16 + lcol) * 2;
        ldmA(a_hi[mi], aH + off);
        ldmA(a_lo[mi], aL + off);
      }
#pragma unroll
      for (int ni = 0; ni < 8; ni++) {
        uint32_t bo = (uint32_t)((wn * 64 + ni * 8 + gid) * LDA2 + ks * 16 + tig * 2) * 2;
        uint32_t bh[2], bl[2];
        bh[0] = lds32(bH + bo); bh[1] = lds32(bH + bo + 16);
        bl[0] = lds32(bL + bo); bl[1] = lds32(bL + bo + 16);
#pragma unroll
        for (int mi = 0; mi < 2; mi++) {
          mma16816(acc[mi][ni], a_hi[mi], bh);
          mma16816(acc[mi][ni], a_hi[mi], bl);
          mma16816(acc[mi][ni], a_lo[mi], bh);
        }
      }
    }
    if (kc < 9) storeA(cur ^ 1);
    CP_WAIT(0);
    __syncthreads();
    if (kc < 8) { cpB(kc + 2, cur); gatherA(kc + 2); }
  }

  float inv = 1.f / (float)APM;
#pragma unroll
  for (int mi = 0; mi < 2; mi++) {
    int r0 = bm + wm * 32 + mi * 16 + gid;
    int r1 = r0 + 8;
    bool v0 = r0 < N, v1 = r1 < N;
    int mol0 = v0 ? (r0 / APM) : 0;
    int mol1 = v1 ? (r1 / APM) : 0;
    float* O0 = out + (size_t)mol0 * H;
    float* O1 = out + (size_t)mol1 * H;
#pragma unroll
    for (int ni = 0; ni < 8; ni++) {
      int n = wn * 64 + ni * 8 + tig * 2;
      float2 bo = *(const float2*)(b_o + n);
      if (v0) {
        float o0 = fmaxf(acc[mi][ni][0] + bo.x, 0.f) * inv;
        float o1 = fmaxf(acc[mi][ni][1] + bo.y, 0.f) * inv;
        red_add2(O0 + n, o0, o1);
      }
      if (v1) {
        float o2 = fmaxf(acc[mi][ni][2] + bo.x, 0.f) * inv;
        float o3 = fmaxf(acc[mi][ni][3] + bo.y, 0.f) * inv;
        red_add2(O1 + n, o2, o3);
      }
    }
  }
}

// ---------------- host ---------------------------------------------------------
extern "C" void kernel_launch(void* const* d_in, const int* in_sizes, int n_in,
                              void* d_out, int out_size) {
  const float* x    = (const float*)d_in[0];
  const float* bond = (const float*)d_in[1];
  const float* W_i  = (const float*)d_in[2];
  const float* W_h  = (const float*)d_in[3];
  const float* W_o  = (const float*)d_in[4];
  const float* b_o  = (const float*)d_in[5];
  const int*   esrc = (const int*)d_in[6];
  const int*   edst = (const int*)d_in[7];
  (void)n_in;

  int N   = in_sizes[0] / AF;
  int E   = in_sizes[1] / BF;
  int NM  = out_size / H;
  int APM = N / NM;

  float *msg_input, *msgA, *msgB, *S0, *S1, *WiT;
  __half *WhH, *WhL, *WoH, *WoL;
  cudaGetSymbolAddress((void**)&msg_input, g_msg_input);
  cudaGetSymbolAddress((void**)&msgA, g_msgA);
  cudaGetSymbolAddress((void**)&msgB, g_msgB);
  cudaGetSymbolAddress((void**)&S0, g_S0);
  cudaGetSymbolAddress((void**)&S1, g_S1);
  cudaGetSymbolAddress((void**)&WiT, g_WiT);
  cudaGetSymbolAddress((void**)&WhH, g_Wh_hi);
  cudaGetSymbolAddress((void**)&WhL, g_Wh_lo);
  cudaGetSymbolAddress((void**)&WoH, g_Wo_hi);
  cudaGetSymbolAddress((void**)&WoL, g_Wo_lo);

  cudaFuncSetAttribute(k_msg, cudaFuncAttributeMaxDynamicSharedMemorySize, SMEM_TC);
  cudaFuncSetAttribute(k_out, cudaFuncAttributeMaxDynamicSharedMemorySize, SMEM_TC);
  size_t smem_init = (size_t)(KI * BM + KI * H) * sizeof(float);
  cudaFuncSetAttribute(k_init, cudaFuncAttributeMaxDynamicSharedMemorySize, (int)smem_init);

  // launch 1: fused prep
  k_prep<<<(H * KO_PAD + 255) / 256, 256>>>(WiT, W_i, WhH, WhL, W_h, WoH, WoL, W_o);

  // launch 2: zero S0; launch 3: init + scatter
  cudaMemsetAsync(S0, 0, (size_t)N * H * sizeof(float));
  int nblk_i = (E + BM - 1) / BM;
  k_init<<<nblk_i, 256, smem_init>>>(x, bond, esrc, edst, WiT, msg_input, msgA, S0, E);

  int nblk_e = (E + 63) / 64;
  float* cur = msgA; float* nxt = msgB;
  float* Scur = S0;  float* Snext = S1;
  for (int it = 0; it < 5; it++) {
    cudaMemsetAsync(Snext, 0, (size_t)N * H * sizeof(float));   // launch 4 (it=0)
    k_msg<<<nblk_e, 256, SMEM_TC>>>(Scur, cur, msg_input, WhH, WhL,
                                    esrc, edst, nxt, Snext, E); // launch 5 (it=0)
    float* t = cur; cur = nxt; nxt = t;
    t = Scur; Scur = Snext; Snext = t;
  }

  cudaMemsetAsync(d_out, 0, (size_t)out_size * sizeof(float));
  int nblk_n = (N + 63) / 64;
  k_out<<<nblk_n, 256, SMEM_TC>>>(x, Scur, WoH, WoL, b_o, (float*)d_out, N, APM);
}